// round 2
// baseline (speedup 1.0000x reference)
#include <cuda_runtime.h>

#define H 2048
#define S 2048
#define V 50257

// ---- scratch ----
__device__ float g_attn_applied[H];
__device__ float g_x[H];
__device__ float g_gx[3 * H];
__device__ float g_gh[3 * H];
__device__ float g_hnew[H];
__device__ float g_logits[V];
__device__ float g_lse[1];

__device__ __forceinline__ float warp_sum(float v) {
#pragma unroll
    for (int o = 16; o > 0; o >>= 1) v += __shfl_down_sync(0xffffffffu, v, o);
    return v;
}
__device__ __forceinline__ float warp_max(float v) {
#pragma unroll
    for (int o = 16; o > 0; o >>= 1) v = fmaxf(v, __shfl_down_sync(0xffffffffu, v, o));
    return v;
}

// Row-dot: 16 float4 weight loads vs smem vector (H = 2048)
__device__ __forceinline__ float dot_row(const float4* __restrict__ w4,
                                         const float4* __restrict__ xs, int lane) {
    float acc = 0.f;
#pragma unroll
    for (int i = 0; i < 16; ++i) {
        float4 wv = __ldg(&w4[i * 32 + lane]);
        float4 xv = xs[i * 32 + lane];
        acc += wv.x * xv.x + wv.y * xv.y + wv.z * xv.z + wv.w * xv.w;
    }
    return acc;
}

// ---- K1 "front": blocks 0..63 = colsum of encoder_outputs (attn weights are all 1.0,
//      softmax over singleton); blocks 64..831 = GRU hh-gates GEMV (depends only on h0).
__global__ void __launch_bounds__(256, 6)
front_kernel(const float* __restrict__ enc,
             const float* __restrict__ w_hh, const float* __restrict__ b_hh,
             const float* __restrict__ h0, float* __restrict__ out_attn) {
    int tid = threadIdx.x;
    if (blockIdx.x < 64) {
        // 64 blocks x 32 cols: each warp sums 256 rows of a 32-col stripe (coalesced 128B/row)
        __shared__ float red[8][32];
        int lane = tid & 31, w = tid >> 5;
        int col = blockIdx.x * 32 + lane;
        const float* p = enc + (size_t)(w * 256) * H + col;
        float acc = 0.f;
#pragma unroll 8
        for (int r = 0; r < 256; ++r) acc += __ldg(&p[(size_t)r * H]);
        red[w][lane] = acc;
        __syncthreads();
        if (w == 0) {
            float s = 0.f;
#pragma unroll
            for (int j = 0; j < 8; ++j) s += red[j][lane];
            g_attn_applied[col] = s;
            out_attn[col] = 1.0f;   // softmax over singleton axis == 1
        }
    } else {
        __shared__ float4 vs[H / 4];
        for (int i = tid; i < H / 4; i += 256) vs[i] = ((const float4*)h0)[i];
        __syncthreads();
        int warp = tid >> 5, lane = tid & 31;
        int r = (blockIdx.x - 64) * 8 + warp;          // 768 blocks * 8 = 6144 rows
        float acc = dot_row((const float4*)(w_hh + (size_t)r * H), vs, lane);
        acc = warp_sum(acc);
        if (lane == 0) g_gh[r] = acc + b_hh[r];
    }
}

// ---- K2: x = relu([embedded, attn_applied] @ comb_w.T + comb_b) ----
__global__ void __launch_bounds__(256, 6)
comb_relu(const float* __restrict__ comb_w, const float* __restrict__ comb_b,
          const float* __restrict__ emb, const int* __restrict__ tok) {
    __shared__ float4 vs[2 * H / 4];  // 16KB: [embedded | attn_applied]
    int tid = threadIdx.x;
    const float4* e4 = (const float4*)(emb + (size_t)tok[0] * H);
    for (int i = tid; i < H / 4; i += 256) {
        vs[i] = __ldg(&e4[i]);
        vs[H / 4 + i] = ((const float4*)g_attn_applied)[i];
    }
    __syncthreads();
    int warp = tid >> 5, lane = tid & 31;
    int h = blockIdx.x * 8 + warp;                      // 256 blocks
    const float4* w4 = (const float4*)(comb_w + (size_t)h * (2 * H));
    float acc = 0.f;
#pragma unroll
    for (int i = 0; i < 32; ++i) {
        float4 wv = __ldg(&w4[i * 32 + lane]);
        float4 xv = vs[i * 32 + lane];
        acc += wv.x * xv.x + wv.y * xv.y + wv.z * xv.z + wv.w * xv.w;
    }
    acc = warp_sum(acc);
    if (lane == 0) g_x[h] = fmaxf(acc + comb_b[h], 0.f);
}

// ---- K3: ih-gates GEMV ----
__global__ void __launch_bounds__(256, 6)
gates_ih(const float* __restrict__ w_ih, const float* __restrict__ b_ih) {
    __shared__ float4 vs[H / 4];
    int tid = threadIdx.x;
    for (int i = tid; i < H / 4; i += 256) vs[i] = ((const float4*)g_x)[i];
    __syncthreads();
    int warp = tid >> 5, lane = tid & 31;
    int r = blockIdx.x * 8 + warp;                      // 768 blocks
    float acc = dot_row((const float4*)(w_ih + (size_t)r * H), vs, lane);
    acc = warp_sum(acc);
    if (lane == 0) g_gx[r] = acc + b_ih[r];
}

// ---- K4: GRU nonlinearity ----
__global__ void gru_combine(const float* __restrict__ h0, float* __restrict__ out_h) {
    int h = blockIdx.x * 256 + threadIdx.x;
    float r = 1.f / (1.f + expf(-(g_gx[h] + g_gh[h])));
    float z = 1.f / (1.f + expf(-(g_gx[H + h] + g_gh[H + h])));
    float n = tanhf(g_gx[2 * H + h] + r * g_gh[2 * H + h]);
    float hn = (1.f - z) * n + z * h0[h];
    g_hnew[h] = hn;
    out_h[h] = hn;
}

// ---- K5: big GEMV, persistent grid, 2 rows/warp ----
#define OG_BLOCKS 760   // 152 SMs * 5 blocks
__global__ void __launch_bounds__(256, 5)
out_gemv(const float* __restrict__ out_w, const float* __restrict__ out_b) {
    __shared__ float4 xs[H / 4];
    int tid = threadIdx.x;
    for (int i = tid; i < H / 4; i += 256) xs[i] = ((const float4*)g_hnew)[i];
    __syncthreads();
    int warp = tid >> 5, lane = tid & 31;
    int gw = blockIdx.x * 8 + warp;                    // 0..6079
    const int stride = OG_BLOCKS * 8 * 2;              // 12160 rows / iter
    for (int r0 = gw * 2; r0 < V; r0 += stride) {
        int r1 = r0 + 1;
        const float4* wa = (const float4*)(out_w + (size_t)r0 * H);
        float a0 = 0.f, a1 = 0.f;
        if (r1 < V) {
            const float4* wb = (const float4*)(out_w + (size_t)r1 * H);
#pragma unroll
            for (int i = 0; i < 16; ++i) {
                float4 xv = xs[i * 32 + lane];
                float4 wv = __ldg(&wa[i * 32 + lane]);
                float4 uv = __ldg(&wb[i * 32 + lane]);
                a0 += wv.x * xv.x + wv.y * xv.y + wv.z * xv.z + wv.w * xv.w;
                a1 += uv.x * xv.x + uv.y * xv.y + uv.z * xv.z + uv.w * xv.w;
            }
        } else {
#pragma unroll
            for (int i = 0; i < 16; ++i) {
                float4 xv = xs[i * 32 + lane];
                float4 wv = __ldg(&wa[i * 32 + lane]);
                a0 += wv.x * xv.x + wv.y * xv.y + wv.z * xv.z + wv.w * xv.w;
            }
        }
        a0 = warp_sum(a0);
        a1 = warp_sum(a1);
        if (lane == 0) {
            g_logits[r0] = a0 + out_b[r0];
            if (r1 < V) g_logits[r1] = a1 + out_b[r1];
        }
    }
}

// ---- K6: logsumexp over logits (L2-resident) ----
__global__ void lse_kernel() {
    __shared__ float red[32];
    __shared__ float red2[32];
    int t = threadIdx.x;
    float m = -1e30f;
#pragma unroll 4
    for (int i = t; i < V; i += 1024) m = fmaxf(m, g_logits[i]);
    m = warp_max(m);
    if ((t & 31) == 0) red[t >> 5] = m;
    __syncthreads();
    if (t < 32) {
        float mm = warp_max(red[t]);
        if (t == 0) red[0] = mm;
    }
    __syncthreads();
    float M = red[0];
    float s = 0.f;
#pragma unroll 4
    for (int i = t; i < V; i += 1024) s += expf(g_logits[i] - M);
    s = warp_sum(s);
    if ((t & 31) == 0) red2[t >> 5] = s;
    __syncthreads();
    if (t == 0) {
        float ss = 0.f;
#pragma unroll
        for (int i = 0; i < 32; ++i) ss += red2[i];
        g_lse[0] = M + logf(ss);
    }
}

// ---- K7: write log_probs ----
__global__ void write_logprobs(float* __restrict__ out) {
    int v = blockIdx.x * 256 + threadIdx.x;
    if (v < V) out[v] = g_logits[v] - g_lse[0];
}

extern "C" void kernel_launch(void* const* d_in, const int* in_sizes, int n_in,
                              void* d_out, int out_size) {
    const int*   tok    = (const int*)d_in[0];
    const float* hidden = (const float*)d_in[1];
    const float* enc    = (const float*)d_in[2];
    const float* emb    = (const float*)d_in[3];
    const float* comb_w = (const float*)d_in[6];
    const float* comb_b = (const float*)d_in[7];
    const float* w_ih   = (const float*)d_in[8];
    const float* w_hh   = (const float*)d_in[9];
    const float* b_ih   = (const float*)d_in[10];
    const float* b_hh   = (const float*)d_in[11];
    const float* out_w  = (const float*)d_in[12];
    const float* out_b  = (const float*)d_in[13];

    float* out      = (float*)d_out;
    float* out_h    = out + V;
    float* out_attn = out + V + H;

    front_kernel<<<832, 256>>>(enc, w_hh, b_hh, hidden, out_attn);
    comb_relu<<<256, 256>>>(comb_w, comb_b, emb, tok);
    gates_ih<<<768, 256>>>(w_ih, b_ih);
    gru_combine<<<8, 256>>>(hidden, out_h);
    out_gemv<<<OG_BLOCKS, 256>>>(out_w, out_b);
    lse_kernel<<<1, 1024>>>();
    write_logprobs<<<(V + 255) / 256, 256>>>(out);
}

// round 3
// speedup vs baseline: 1.1199x; 1.1199x over previous
#include <cuda_runtime.h>

#define H 2048
#define S 2048
#define V 50257
#define CHUNKS 32

// ---- scratch ----
__device__ float g_attn_partial[CHUNKS * H];
__device__ float g_attn_applied[H];
__device__ float g_x[H];
__device__ float g_gx[3 * H];
__device__ float g_gh[3 * H];
__device__ float g_hnew[H];
__device__ float g_logits[V];
__device__ float g_lse[1];
__device__ int   g_counter;

__device__ __forceinline__ float warp_sum(float v) {
#pragma unroll
    for (int o = 16; o > 0; o >>= 1) v += __shfl_down_sync(0xffffffffu, v, o);
    return v;
}
__device__ __forceinline__ float warp_max(float v) {
#pragma unroll
    for (int o = 16; o > 0; o >>= 1) v = fmaxf(v, __shfl_down_sync(0xffffffffu, v, o));
    return v;
}

// ---- A: partial column sums of encoder_outputs (attn_weights are all 1.0) ----
__global__ void colsum_partial(const float* __restrict__ enc) {
    int col = blockIdx.x * 256 + threadIdx.x;          // 8 col-blocks
    int s0 = blockIdx.y * (S / CHUNKS);                // 32 row-chunks of 64
    float acc = 0.f;
#pragma unroll 8
    for (int s = 0; s < S / CHUNKS; ++s)
        acc += __ldg(&enc[(size_t)(s0 + s) * H + col]);
    g_attn_partial[blockIdx.y * H + col] = acc;
}

// ---- R: reduce partials -> attn_applied; emit attn_weights (=1.0); reset counter ----
__global__ void colsum_reduce(float* __restrict__ out_attn) {
    int h = blockIdx.x * 256 + threadIdx.x;
    float acc = 0.f;
#pragma unroll
    for (int c = 0; c < CHUNKS; ++c) acc += g_attn_partial[c * H + h];
    g_attn_applied[h] = acc;
    out_attn[h] = 1.0f;
    if (h == 0) g_counter = 0;
}

// ---- B: x = relu( [embedded, attn_applied] @ comb_w.T + comb_b ) ----
__global__ void comb_relu(const float* __restrict__ comb_w,
                          const float* __restrict__ comb_b,
                          const float* __restrict__ emb,
                          const int* __restrict__ tok) {
    int warp = threadIdx.x >> 5, lane = threadIdx.x & 31;
    int h = blockIdx.x * 8 + warp;
    const float4* w4 = (const float4*)(comb_w + (size_t)h * (2 * H));
    const float4* e4 = (const float4*)(emb + (size_t)tok[0] * H);
    const float4* a4 = (const float4*)g_attn_applied;
    float acc = 0.f;
#pragma unroll
    for (int i = 0; i < 16; ++i) {
        float4 wv = __ldg(&w4[i * 32 + lane]);
        float4 xv = __ldg(&e4[i * 32 + lane]);
        acc += wv.x * xv.x + wv.y * xv.y + wv.z * xv.z + wv.w * xv.w;
    }
    const float4* w2 = w4 + 512;
#pragma unroll
    for (int i = 0; i < 16; ++i) {
        float4 wv = __ldg(&w2[i * 32 + lane]);
        float4 xv = a4[i * 32 + lane];
        acc += wv.x * xv.x + wv.y * xv.y + wv.z * xv.z + wv.w * xv.w;
    }
    acc = warp_sum(acc);
    if (lane == 0) g_x[h] = fmaxf(acc + comb_b[h], 0.f);
}

// ---- C: both GRU gate GEMVs, single wave (768 blocks), 2 sequential rows/warp.
//      Last block computes the GRU nonlinearity (fused gru_combine). ----
#define GATES_BLOCKS 768
__global__ void gates(const float* __restrict__ w_ih, const float* __restrict__ w_hh,
                      const float* __restrict__ b_ih, const float* __restrict__ b_hh,
                      const float* __restrict__ h0, float* __restrict__ out_h) {
    __shared__ float4 vx[H / 4];   // g_x
    __shared__ float4 vh[H / 4];   // h0
    int tid = threadIdx.x;
    for (int i = tid; i < H / 4; i += 256) {
        vx[i] = ((const float4*)g_x)[i];
        vh[i] = __ldg(&((const float4*)h0)[i]);
    }
    __syncthreads();
    int warp = tid >> 5, lane = tid & 31;
    int gw = blockIdx.x * 8 + warp;                    // 0..6143
#pragma unroll
    for (int k = 0; k < 2; ++k) {
        int row = gw * 2 + k;                          // 0..12287
        const float* w; const float4* vec; const float* bias; float* dst; int r;
        if (row < 3 * H) { r = row;         w = w_ih; vec = vx; bias = b_ih; dst = g_gx; }
        else             { r = row - 3 * H; w = w_hh; vec = vh; bias = b_hh; dst = g_gh; }
        const float4* w4 = (const float4*)(w + (size_t)r * H);
        float acc = 0.f;
#pragma unroll
        for (int i = 0; i < 16; ++i) {
            float4 wv = __ldg(&w4[i * 32 + lane]);
            float4 xv = vec[i * 32 + lane];
            acc += wv.x * xv.x + wv.y * xv.y + wv.z * xv.z + wv.w * xv.w;
        }
        acc = warp_sum(acc);
        if (lane == 0) dst[r] = acc + bias[r];
    }
    // ---- fused gru_combine: last block to finish does the elementwise tail ----
    __shared__ int s_last;
    __threadfence();
    __syncthreads();
    if (tid == 0) s_last = (atomicAdd(&g_counter, 1) == GATES_BLOCKS - 1);
    __syncthreads();
    if (s_last) {
        __threadfence();  // acquire: see all other blocks' g_gx/g_gh writes
#pragma unroll
        for (int j = 0; j < 8; ++j) {
            int h = j * 256 + tid;
            float r = 1.f / (1.f + __expf(-(g_gx[h] + g_gh[h])));
            float z = 1.f / (1.f + __expf(-(g_gx[H + h] + g_gh[H + h])));
            float n = tanhf(g_gx[2 * H + h] + r * g_gh[2 * H + h]);
            float hn = (1.f - z) * n + z * __ldg(&h0[h]);
            g_hnew[h] = hn;
            out_h[h] = hn;
        }
    }
}

// ---- E: big GEMV (R1 form, known-good ~6.6 TB/s) ----
__global__ void out_gemv(const float* __restrict__ out_w, const float* __restrict__ out_b) {
    __shared__ float4 hs[H / 4];
    for (int i = threadIdx.x; i < H / 4; i += 256)
        hs[i] = ((const float4*)g_hnew)[i];
    __syncthreads();
    int warp = threadIdx.x >> 5, lane = threadIdx.x & 31;
    int v = blockIdx.x * 8 + warp;
    if (v >= V) return;
    const float4* w4 = (const float4*)(out_w + (size_t)v * H);
    float acc = 0.f;
#pragma unroll
    for (int i = 0; i < 16; ++i) {
        float4 wv = __ldg(&w4[i * 32 + lane]);
        float4 xv = hs[i * 32 + lane];
        acc += wv.x * xv.x + wv.y * xv.y + wv.z * xv.z + wv.w * xv.w;
    }
    acc = warp_sum(acc);
    if (lane == 0) g_logits[v] = acc + out_b[v];
}

// ---- F1: logsumexp over logits ----
__global__ void lse_kernel() {
    __shared__ float red[32];
    __shared__ float red2[32];
    int t = threadIdx.x;
    float m = -1e30f;
    for (int i = t; i < V; i += 1024) m = fmaxf(m, g_logits[i]);
    m = warp_max(m);
    if ((t & 31) == 0) red[t >> 5] = m;
    __syncthreads();
    if (t < 32) {
        float mm = warp_max(red[t]);
        if (t == 0) red[0] = mm;
    }
    __syncthreads();
    float M = red[0];
    float s = 0.f;
    for (int i = t; i < V; i += 1024) s += expf(g_logits[i] - M);
    s = warp_sum(s);
    if ((t & 31) == 0) red2[t >> 5] = s;
    __syncthreads();
    if (t == 0) {
        float ss = 0.f;
#pragma unroll
        for (int i = 0; i < 32; ++i) ss += red2[i];
        g_lse[0] = M + logf(ss);
    }
}

// ---- F2: write log_probs ----
__global__ void write_logprobs(float* __restrict__ out) {
    int v = blockIdx.x * 256 + threadIdx.x;
    if (v < V) out[v] = g_logits[v] - g_lse[0];
}

extern "C" void kernel_launch(void* const* d_in, const int* in_sizes, int n_in,
                              void* d_out, int out_size) {
    const int*   tok    = (const int*)d_in[0];
    const float* hidden = (const float*)d_in[1];
    const float* enc    = (const float*)d_in[2];
    const float* emb    = (const float*)d_in[3];
    const float* comb_w = (const float*)d_in[6];
    const float* comb_b = (const float*)d_in[7];
    const float* w_ih   = (const float*)d_in[8];
    const float* w_hh   = (const float*)d_in[9];
    const float* b_ih   = (const float*)d_in[10];
    const float* b_hh   = (const float*)d_in[11];
    const float* out_w  = (const float*)d_in[12];
    const float* out_b  = (const float*)d_in[13];

    float* out      = (float*)d_out;
    float* out_h    = out + V;
    float* out_attn = out + V + H;

    colsum_partial<<<dim3(8, 32), 256>>>(enc);
    colsum_reduce<<<8, 256>>>(out_attn);
    comb_relu<<<256, 256>>>(comb_w, comb_b, emb, tok);
    gates<<<GATES_BLOCKS, 256>>>(w_ih, w_hh, b_ih, b_hh, hidden, out_h);
    out_gemv<<<(V + 7) / 8, 256>>>(out_w, out_b);
    lse_kernel<<<1, 1024>>>();
    write_logprobs<<<(V + 255) / 256, 256>>>(out);
}